// round 11
// baseline (speedup 1.0000x reference)
#include <cuda_runtime.h>
#include <cuda_fp16.h>
#include <stdint.h>
#include <math.h>

// ---------------------------------------------------------------------------
// MoE: gate -> top2 route -> capacity dispatch -> 8x SwiGLU expert MLP -> combine
// Expert GEMMs: mma.sync fp16 (fp32 acc), persistent CTAs, TK=64, 3-slot ring.
// R11: side-stream overlap (routing chain || weight transpose), count fused
// into gate, ballot-based pos ranking, fp16 expert-output buffer.
// ---------------------------------------------------------------------------

#define N_TOK   16384
#define DM      1024
#define NE      8
#define CAP     4096
#define DFF     3072
#define DH      1536
#define NSLOT   (N_TOK * 2)
#define NBLK    32

// GEMM tiling
#define TM      128
#define TN      256
#define TK      64
#define ROWB    160                   // 128B data + 32B pad (conflict-free ldmatrix)
#define STAGE_B 61440                 // A: 128*160  +  B: 256*160
#define EP_OFF  (3 * STAGE_B)
#define GEMM_SMEM (EP_OFF + 128 * 136 * 2)   // 219136

// ---- scratch (device globals: allocation-free rule) ----
__device__ __half g_eo[(size_t)NE * CAP * DM];     // expert output (fp16)
__device__ __half g_ax[(size_t)NE * CAP * DM];     // dispatched x (fp16)
__device__ __half g_hg[(size_t)NE * CAP * DH];     // swiglu out (fp16)
__device__ __half g_w1[(size_t)NE * DFF * DM];     // W1^T interleaved [E][3072][1024]
__device__ __half g_w2[(size_t)NE * DM * DH];      // W2^T [E][1024][1536]
__device__ int   g_se[NSLOT];
__device__ float g_sw[NSLOT];
__device__ int   g_sp[NSLOT];
__device__ int   g_bcnt[NBLK * NE];
__device__ int   g_boff[NBLK * NE];

// ---------------------------------------------------------------------------
// helpers
// ---------------------------------------------------------------------------
__device__ __forceinline__ uint32_t smem_u32(const void* p) {
    uint32_t a;
    asm("{ .reg .u64 t; cvta.to.shared.u64 t, %1; cvt.u32.u64 %0, t; }"
        : "=r"(a) : "l"(p));
    return a;
}
__device__ __forceinline__ void cp16(uint32_t dst, const void* src) {
    asm volatile("cp.async.cg.shared.global [%0], [%1], 16;" :: "r"(dst), "l"(src));
}
#define CP_COMMIT() asm volatile("cp.async.commit_group;" ::: "memory")

#define LDSM4(v, addr) \
    asm volatile("ldmatrix.sync.aligned.m8n8.x4.shared.b16 {%0,%1,%2,%3}, [%4];" \
        : "=r"((v)[0]), "=r"((v)[1]), "=r"((v)[2]), "=r"((v)[3]) : "r"(addr))

#define MMA16816(c, a, b0, b1) \
    asm volatile("mma.sync.aligned.m16n8k16.row.col.f32.f16.f16.f32 " \
        "{%0,%1,%2,%3}, {%4,%5,%6,%7}, {%8,%9}, {%0,%1,%2,%3};" \
        : "+f"((c)[0]), "+f"((c)[1]), "+f"((c)[2]), "+f"((c)[3]) \
        : "r"((a)[0]), "r"((a)[1]), "r"((a)[2]), "r"((a)[3]), "r"(b0), "r"(b1))

// ---------------------------------------------------------------------------
// Gate: logits -> softmax -> top2 (ties: lowest index) + fused slot counting
// Block b = 4 tokens = slots 8b..8b+7, all within scan-block (b>>7).
// ---------------------------------------------------------------------------
__global__ void gate_kernel(const float* __restrict__ x, const float* __restrict__ wg) {
    __shared__ float wgs[NE][DM];
    const int tid = threadIdx.x;
    for (int i = tid; i < NE * DM; i += blockDim.x)
        wgs[i & 7][i >> 3] = wg[i];
    __syncthreads();

    const int warp = tid >> 5, lane = tid & 31;
    const int n = blockIdx.x * 4 + warp;

    float acc[NE];
    #pragma unroll
    for (int e = 0; e < NE; e++) acc[e] = 0.f;
    const float* xr = x + (size_t)n * DM;
    for (int j = lane; j < DM; j += 32) {
        const float xv = xr[j];
        #pragma unroll
        for (int e = 0; e < NE; e++) acc[e] += xv * wgs[e][j];
    }
    #pragma unroll
    for (int off = 16; off; off >>= 1)
        #pragma unroll
        for (int e = 0; e < NE; e++)
            acc[e] += __shfl_xor_sync(0xffffffffu, acc[e], off);

    if (lane == 0) {
        float m = acc[0];
        #pragma unroll
        for (int e = 1; e < NE; e++) m = fmaxf(m, acc[e]);
        float p[NE], s = 0.f;
        #pragma unroll
        for (int e = 0; e < NE; e++) { p[e] = expf(acc[e] - m); s += p[e]; }
        const float inv = 1.f / s;
        #pragma unroll
        for (int e = 0; e < NE; e++) p[e] *= inv;
        int e1 = 0;
        #pragma unroll
        for (int e = 1; e < NE; e++) if (p[e] > p[e1]) e1 = e;
        int e2 = (e1 == 0) ? 1 : 0;
        #pragma unroll
        for (int e = 0; e < NE; e++) if (e != e1 && p[e] > p[e2]) e2 = e;
        g_se[2*n]   = e1;  g_sw[2*n]   = p[e1];
        g_se[2*n+1] = e2;  g_sw[2*n+1] = p[e2];
        // fused count (scan-block = blockIdx.x >> 7)
        int* bc = &g_bcnt[(blockIdx.x >> 7) * NE];
        atomicAdd(&bc[e1], 1);
        atomicAdd(&bc[e2], 1);
    }
}

// ---------------------------------------------------------------------------
// Scan: per-expert exclusive block offsets (8 threads)
// ---------------------------------------------------------------------------
__global__ void scan_kernel() {
    const int e = threadIdx.x;
    int run = 0;
    for (int b = 0; b < NBLK; b++) { g_boff[b * NE + e] = run; run += g_bcnt[b * NE + e]; }
}

// ---------------------------------------------------------------------------
// Pos: ballot-based intra-block rank (match_any + warp histograms)
// ---------------------------------------------------------------------------
__global__ void pos_kernel() {
    __shared__ int shcnt[32][NE];
    const int t = threadIdx.x, w = t >> 5, l = t & 31;
    if (t < 32 * NE) ((int*)shcnt)[t] = 0;
    __syncthreads();
    const int s = blockIdx.x * 1024 + t;
    const int e = g_se[s];
    const unsigned mask = __match_any_sync(0xffffffffu, e);
    const int myrank = __popc(mask & ((1u << l) - 1));
    if (l == __ffs(mask) - 1) shcnt[w][e] = __popc(mask);
    __syncthreads();
    int r = g_boff[blockIdx.x * NE + e] + myrank;
    for (int w2 = 0; w2 < w; w2++) r += shcnt[w2][e];
    g_sp[s] = (r < CAP) ? r : -1;
}

// ---------------------------------------------------------------------------
// Scatter: x rows -> fp16 into exp slot
// ---------------------------------------------------------------------------
__global__ void scatter_fp16(const float* __restrict__ x) {
    const int s = blockIdx.x;
    const int p = g_sp[s];
    if (p < 0) return;
    const int e = g_se[s];
    const int tok = s >> 1;
    const float4 v = ((const float4*)(x + (size_t)tok * DM))[threadIdx.x];
    __half h[4] = { __float2half(v.x), __float2half(v.y),
                    __float2half(v.z), __float2half(v.w) };
    *(uint2*)&g_ax[((size_t)e * CAP + p) * DM + threadIdx.x * 4] = *(uint2*)h;
}

// ---------------------------------------------------------------------------
// Weight transpose -> fp16. which==0 (W1): interleave dest rows so that
//   dest row 2j   = fc column j         (a / silu input)
//   dest row 2j+1 = fc column j + 1536  (g / gate input)
// which==1 (W2): plain transpose.
// ---------------------------------------------------------------------------
__global__ void wsplit_kernel(const float* __restrict__ W, const int which,
                              const int K, const int N) {
    __shared__ float s[32][33];
    __half* D = which ? g_w2 : g_w1;
    const int e = blockIdx.z;
    const int n0 = blockIdx.x * 32, k0 = blockIdx.y * 32;
    const float* src = W + (size_t)e * K * N;
    const int tx = threadIdx.x, ty = threadIdx.y;   // 32 x 8

    int scol;
    if (which == 0) scol = (tx < 16) ? (n0 / 2 + tx) : (n0 / 2 + DH + (tx - 16));
    else            scol = n0 + tx;

    #pragma unroll
    for (int i = 0; i < 4; i++)
        s[ty + i*8][tx] = src[(size_t)(k0 + ty + i*8) * N + scol];
    __syncthreads();

    const size_t dbase = (size_t)e * N * K;
    #pragma unroll
    for (int i = 0; i < 4; i++) {
        const int r = ty + i*8;
        const int c = which == 0 ? ((r & 1) ? 16 + (r >> 1) : (r >> 1)) : r;
        D[dbase + (size_t)(n0 + r) * K + k0 + tx] = __float2half(s[tx][c]);
    }
}

// ---------------------------------------------------------------------------
// Persistent batched GEMM: C[e][M][N] = A[e][M][K] @ B[e][N][K]^T (fp16, f32 acc)
// which==0: epilogue = fused SwiGLU, smem-staged, fp16 -> g_hg.
// which==1: fp16 (half2) stores -> g_eo.
// ---------------------------------------------------------------------------
__device__ __forceinline__ void load_stage(
    uint32_t sdst,
    const __half* __restrict__ A, const __half* __restrict__ B,
    const int K, const int k0, const int tid)
{
    #pragma unroll
    for (int i = 0; i < 12; i++) {
        const int L = i * 256 + tid;          // 0..3071
        const int rid = L >> 3, q = L & 7;
        const __half* src;
        uint32_t dst;
        if (rid < 128) { src = A + (size_t)rid * K;                 dst = sdst +         rid * ROWB; }
        else           { const int r = rid - 128; src = B + (size_t)r * K; dst = sdst + 20480 + r * ROWB; }
        cp16(dst + q * 16, src + k0 + q * 8);
    }
}

__global__ void __launch_bounds__(256, 1)
gemm_mma(const int which, const int N, const int K)
{
    extern __shared__ char smem[];
    const uint32_t sb = smem_u32(smem);
    const int tid = threadIdx.x, wid = tid >> 5, lane = tid & 31;
    const int wm = wid & 1, wn = wid >> 1;          // 2 x 4 warp grid, warp 64x64
    const int gq = lane >> 2, tg = lane & 3;

    const __half *gA, *gB;
    if (which == 0) { gA = g_ax; gB = g_w1; }
    else            { gA = g_hg; gB = g_w2; }

    const int nbx = N / TN;
    const int per_e = nbx * (CAP / TM);
    const int NT = per_e * NE;
    const int NC = gridDim.x;
    const int myNT = (NT - (int)blockIdx.x + NC - 1) / NC;
    if (myNT <= 0) return;
    const int T = K / TK;                 // 16 (gemm1) / 24 (gemm2)
    const int G = myNT * T;

    // ---- loader state ----
    int l_t, l_tc = 0, l_tile = blockIdx.x;
    const __half *lA, *lB;
    {
        const int e = l_tile / per_e, r = l_tile % per_e;
        lA = gA + ((size_t)e * CAP + (r / nbx) * TM) * K;
        lB = gB + ((size_t)e * N + (r % nbx) * TN) * K;
    }
    load_stage(sb,           lA, lB, K, 0,  tid);  CP_COMMIT();
    load_stage(sb + STAGE_B, lA, lB, K, TK, tid);  CP_COMMIT();
    l_t = 2;

    const int lmr = lane & 15;
    const int lmk = (lane >> 4) << 3;

    int g = 0;
    int c_tile = blockIdx.x;
    for (int tc = 0; tc < myNT; tc++, c_tile += NC) {
        float acc[128];
        #pragma unroll
        for (int i = 0; i < 128; i++) acc[i] = 0.f;

        for (int t = 0; t < T; t++, g++) {
            if (g + 1 < G) asm volatile("cp.async.wait_group 1;" ::: "memory");
            else           asm volatile("cp.async.wait_group 0;" ::: "memory");
            __syncthreads();

            if (g + 2 < G) {
                load_stage(sb + ((g + 2) % 3) * STAGE_B, lA, lB, K, l_t * TK, tid);
                CP_COMMIT();
                if (++l_t == T) {
                    l_t = 0; l_tc++; l_tile += NC;
                    if (l_tc < myNT) {
                        const int e = l_tile / per_e, r = l_tile % per_e;
                        lA = gA + ((size_t)e * CAP + (r / nbx) * TM) * K;
                        lB = gB + ((size_t)e * N + (r % nbx) * TN) * K;
                    }
                }
            }

            const uint32_t sst = sb + (g % 3) * STAGE_B;
            #pragma unroll
            for (int kk = 0; kk < 4; kk++) {
                const uint32_t koff = (kk * 16 + lmk) * 2;
                const uint32_t aA = sst + (wm * 64 + lmr) * ROWB + koff;
                const uint32_t aB = sst + 20480 + (wn * 64 + lmr) * ROWB + koff;

                uint32_t ah[16], bh[16], q[4];
                LDSM4(&ah[0],  aA);
                LDSM4(&ah[4],  aA + 16 * ROWB);
                LDSM4(&ah[8],  aA + 32 * ROWB);
                LDSM4(&ah[12], aA + 48 * ROWB);
                #pragma unroll
                for (int u = 0; u < 4; u++) {
                    LDSM4(q, aB + u * 16 * ROWB);
                    bh[4*u+0] = q[0]; bh[4*u+1] = q[2]; bh[4*u+2] = q[1]; bh[4*u+3] = q[3];
                }
                #pragma unroll
                for (int i = 0; i < 4; i++)
                    #pragma unroll
                    for (int j = 0; j < 8; j++)
                        MMA16816(&acc[(i*8+j)*4], &ah[i*4], bh[2*j], bh[2*j+1]);
            }
        }

        // ---- epilogue for c_tile ----
        const int e = c_tile / per_e, r = c_tile % per_e;
        const int bm = (r / nbx) * TM, bn = (r % nbx) * TN;

        if (which == 0) {
            __half* EP = (__half*)(smem + EP_OFF);
            #pragma unroll
            for (int i = 0; i < 4; i++) {
                const int lr = wm * 64 + i * 16 + gq;
                #pragma unroll
                for (int j = 0; j < 8; j++) {
                    const int lc = wn * 32 + j * 4 + tg;
                    const float* c = &acc[(i*8+j)*4];
                    const float h0 = (c[0] / (1.f + expf(-c[0]))) * c[1];
                    const float h1 = (c[2] / (1.f + expf(-c[2]))) * c[3];
                    EP[lr * 136 + lc]       = __float2half(h0);
                    EP[(lr + 8) * 136 + lc] = __float2half(h1);
                }
            }
            __syncthreads();
            __half* HG = g_hg + (size_t)e * CAP * DH + (bn >> 1);
            #pragma unroll
            for (int it = 0; it < 8; it++) {
                const int idx = it * 256 + tid;
                const int rr = idx >> 4, qq = idx & 15;
                *(uint4*)&HG[(size_t)(bm + rr) * DH + qq * 8] =
                    *(uint4*)&EP[rr * 136 + qq * 8];
            }
            __syncthreads();   // EP reuse safe next tile
        } else {
            __half* C = g_eo + (size_t)e * CAP * N;
            #pragma unroll
            for (int i = 0; i < 4; i++) {
                const int row = bm + wm * 64 + i * 16 + gq;
                #pragma unroll
                for (int j = 0; j < 8; j++) {
                    const int col = bn + wn * 64 + j * 8 + tg * 2;
                    const float* c = &acc[(i*8+j)*4];
                    *(__half2*)&C[(size_t)row * N + col] = __floats2half2_rn(c[0], c[1]);
                    *(__half2*)&C[(size_t)(row + 8) * N + col] = __floats2half2_rn(c[2], c[3]);
                }
            }
        }
    }
}

// ---------------------------------------------------------------------------
// Combine: out[n] = w0*eo[e0,p0] + w1*eo[e1,p1]   (eo is fp16)
// ---------------------------------------------------------------------------
__global__ void combine_kernel(float* __restrict__ out) {
    const int n = blockIdx.x;
    const int s0 = 2 * n;
    float w0 = g_sw[s0], w1 = g_sw[s0 + 1];
    int   p0 = g_sp[s0], p1 = g_sp[s0 + 1];
    const int e0 = g_se[s0], e1 = g_se[s0 + 1];
    if (p0 < 0) { w0 = 0.f; p0 = 0; }
    if (p1 < 0) { w1 = 0.f; p1 = 0; }
    const uint2 ua = *(const uint2*)&g_eo[((size_t)e0 * CAP + p0) * DM + threadIdx.x * 4];
    const uint2 ub = *(const uint2*)&g_eo[((size_t)e1 * CAP + p1) * DM + threadIdx.x * 4];
    const float2 a0 = __half22float2(*(const __half2*)&ua.x);
    const float2 a1 = __half22float2(*(const __half2*)&ua.y);
    const float2 b0 = __half22float2(*(const __half2*)&ub.x);
    const float2 b1 = __half22float2(*(const __half2*)&ub.y);
    float4 o;
    o.x = w0 * a0.x + w1 * b0.x;
    o.y = w0 * a0.y + w1 * b0.y;
    o.z = w0 * a1.x + w1 * b1.x;
    o.w = w0 * a1.y + w1 * b1.y;
    ((float4*)(out + (size_t)n * DM))[threadIdx.x] = o;
}

// ---------------------------------------------------------------------------
extern "C" void kernel_launch(void* const* d_in, const int* in_sizes, int n_in,
                              void* d_out, int out_size) {
    const float *x = nullptr, *wg = nullptr, *cfc = nullptr, *cpr = nullptr;
    for (int i = 0; i < n_in; i++) {
        switch (in_sizes[i]) {
            case 16777216: x   = (const float*)d_in[i]; break;  // [8,2048,1024]
            case 8192:     wg  = (const float*)d_in[i]; break;  // [1024,8]
            case 25165824: cfc = (const float*)d_in[i]; break;  // [8,1024,3072]
            case 12582912: cpr = (const float*)d_in[i]; break;  // [8,1536,1024]
        }
    }
    float* out = (float*)d_out;

    int nsm = 148;
    cudaDeviceGetAttribute(&nsm, cudaDevAttrMultiProcessorCount, 0);
    cudaFuncSetAttribute(gemm_mma, cudaFuncAttributeMaxDynamicSharedMemorySize, GEMM_SMEM);

    // One-time host resources (no device memory; deterministic work per call)
    static cudaStream_t s2 = nullptr;
    static cudaEvent_t evF = nullptr, evJ = nullptr;
    if (!s2) {
        cudaStreamCreateWithFlags(&s2, cudaStreamNonBlocking);
        cudaEventCreateWithFlags(&evF, cudaEventDisableTiming);
        cudaEventCreateWithFlags(&evJ, cudaEventDisableTiming);
    }
    void* bcnt_ptr = nullptr;
    cudaGetSymbolAddress(&bcnt_ptr, g_bcnt);

    // Fork: routing chain on s2, weight transposes on main (capture) stream
    cudaEventRecord(evF, 0);
    cudaStreamWaitEvent(s2, evF, 0);

    cudaMemsetAsync(bcnt_ptr, 0, NBLK * NE * sizeof(int), s2);
    gate_kernel  <<<N_TOK / 4, 128, 0, s2>>>(x, wg);
    scan_kernel  <<<1, NE, 0, s2>>>();
    pos_kernel   <<<NBLK, 1024, 0, s2>>>();
    scatter_fp16 <<<NSLOT, 256, 0, s2>>>(x);
    cudaEventRecord(evJ, s2);

    wsplit_kernel<<<dim3(DFF / 32, DM / 32, NE), dim3(32, 8)>>>(cfc, 0, DM, DFF);  // W1 (interleaved)
    wsplit_kernel<<<dim3(DM / 32, DH / 32, NE), dim3(32, 8)>>>(cpr, 1, DH, DM);    // W2

    cudaStreamWaitEvent(0, evJ, 0);   // join before GEMM1 (needs g_ax + g_w1)

    gemm_mma<<<nsm, 256, GEMM_SMEM>>>(0, DFF, DM);   // fused H+SwiGLU -> g_hg
    gemm_mma<<<nsm, 256, GEMM_SMEM>>>(1, DM, DH);    // O = HG @ W2^T -> g_eo (fp16)

    combine_kernel<<<N_TOK, 256>>>(out);
}

// round 12
// speedup vs baseline: 1.0051x; 1.0051x over previous
#include <cuda_runtime.h>
#include <cuda_fp16.h>
#include <stdint.h>
#include <math.h>

// ---------------------------------------------------------------------------
// MoE: gate -> top2 route -> capacity dispatch -> 8x SwiGLU expert MLP -> combine
// Expert GEMMs: mma.sync fp16 (fp32 acc), persistent CTAs, TK=64, 3-slot ring.
// R12: single stream (R11 fork/join regressed); keep fused count, ballot pos,
// fp16 expert-output; scatter with ILP=2.
// ---------------------------------------------------------------------------

#define N_TOK   16384
#define DM      1024
#define NE      8
#define CAP     4096
#define DFF     3072
#define DH      1536
#define NSLOT   (N_TOK * 2)
#define NBLK    32

// GEMM tiling
#define TM      128
#define TN      256
#define TK      64
#define ROWB    160                   // 128B data + 32B pad (conflict-free ldmatrix)
#define STAGE_B 61440                 // A: 128*160  +  B: 256*160
#define EP_OFF  (3 * STAGE_B)
#define GEMM_SMEM (EP_OFF + 128 * 136 * 2)   // 219136

// ---- scratch (device globals: allocation-free rule) ----
__device__ __half g_eo[(size_t)NE * CAP * DM];     // expert output (fp16)
__device__ __half g_ax[(size_t)NE * CAP * DM];     // dispatched x (fp16)
__device__ __half g_hg[(size_t)NE * CAP * DH];     // swiglu out (fp16)
__device__ __half g_w1[(size_t)NE * DFF * DM];     // W1^T interleaved [E][3072][1024]
__device__ __half g_w2[(size_t)NE * DM * DH];      // W2^T [E][1024][1536]
__device__ int   g_se[NSLOT];
__device__ float g_sw[NSLOT];
__device__ int   g_sp[NSLOT];
__device__ int   g_bcnt[NBLK * NE];
__device__ int   g_boff[NBLK * NE];

// ---------------------------------------------------------------------------
// helpers
// ---------------------------------------------------------------------------
__device__ __forceinline__ uint32_t smem_u32(const void* p) {
    uint32_t a;
    asm("{ .reg .u64 t; cvta.to.shared.u64 t, %1; cvt.u32.u64 %0, t; }"
        : "=r"(a) : "l"(p));
    return a;
}
__device__ __forceinline__ void cp16(uint32_t dst, const void* src) {
    asm volatile("cp.async.cg.shared.global [%0], [%1], 16;" :: "r"(dst), "l"(src));
}
#define CP_COMMIT() asm volatile("cp.async.commit_group;" ::: "memory")

#define LDSM4(v, addr) \
    asm volatile("ldmatrix.sync.aligned.m8n8.x4.shared.b16 {%0,%1,%2,%3}, [%4];" \
        : "=r"((v)[0]), "=r"((v)[1]), "=r"((v)[2]), "=r"((v)[3]) : "r"(addr))

#define MMA16816(c, a, b0, b1) \
    asm volatile("mma.sync.aligned.m16n8k16.row.col.f32.f16.f16.f32 " \
        "{%0,%1,%2,%3}, {%4,%5,%6,%7}, {%8,%9}, {%0,%1,%2,%3};" \
        : "+f"((c)[0]), "+f"((c)[1]), "+f"((c)[2]), "+f"((c)[3]) \
        : "r"((a)[0]), "r"((a)[1]), "r"((a)[2]), "r"((a)[3]), "r"(b0), "r"(b1))

// ---------------------------------------------------------------------------
// Gate: logits -> softmax -> top2 (ties: lowest index) + fused slot counting
// Block b = 4 tokens; all 8 slots fall in scan-block (b>>7).
// ---------------------------------------------------------------------------
__global__ void gate_kernel(const float* __restrict__ x, const float* __restrict__ wg) {
    __shared__ float wgs[NE][DM];
    const int tid = threadIdx.x;
    for (int i = tid; i < NE * DM; i += blockDim.x)
        wgs[i & 7][i >> 3] = wg[i];
    __syncthreads();

    const int warp = tid >> 5, lane = tid & 31;
    const int n = blockIdx.x * 4 + warp;

    float acc[NE];
    #pragma unroll
    for (int e = 0; e < NE; e++) acc[e] = 0.f;
    const float* xr = x + (size_t)n * DM;
    for (int j = lane; j < DM; j += 32) {
        const float xv = xr[j];
        #pragma unroll
        for (int e = 0; e < NE; e++) acc[e] += xv * wgs[e][j];
    }
    #pragma unroll
    for (int off = 16; off; off >>= 1)
        #pragma unroll
        for (int e = 0; e < NE; e++)
            acc[e] += __shfl_xor_sync(0xffffffffu, acc[e], off);

    if (lane == 0) {
        float m = acc[0];
        #pragma unroll
        for (int e = 1; e < NE; e++) m = fmaxf(m, acc[e]);
        float p[NE], s = 0.f;
        #pragma unroll
        for (int e = 0; e < NE; e++) { p[e] = expf(acc[e] - m); s += p[e]; }
        const float inv = 1.f / s;
        #pragma unroll
        for (int e = 0; e < NE; e++) p[e] *= inv;
        int e1 = 0;
        #pragma unroll
        for (int e = 1; e < NE; e++) if (p[e] > p[e1]) e1 = e;
        int e2 = (e1 == 0) ? 1 : 0;
        #pragma unroll
        for (int e = 0; e < NE; e++) if (e != e1 && p[e] > p[e2]) e2 = e;
        g_se[2*n]   = e1;  g_sw[2*n]   = p[e1];
        g_se[2*n+1] = e2;  g_sw[2*n+1] = p[e2];
        int* bc = &g_bcnt[(blockIdx.x >> 7) * NE];
        atomicAdd(&bc[e1], 1);
        atomicAdd(&bc[e2], 1);
    }
}

// ---------------------------------------------------------------------------
// Scan: per-expert exclusive block offsets (8 threads)
// ---------------------------------------------------------------------------
__global__ void scan_kernel() {
    const int e = threadIdx.x;
    int run = 0;
    for (int b = 0; b < NBLK; b++) { g_boff[b * NE + e] = run; run += g_bcnt[b * NE + e]; }
}

// ---------------------------------------------------------------------------
// Pos: ballot-based intra-block rank (match_any + warp histograms)
// ---------------------------------------------------------------------------
__global__ void pos_kernel() {
    __shared__ int shcnt[32][NE];
    const int t = threadIdx.x, w = t >> 5, l = t & 31;
    if (t < 32 * NE) ((int*)shcnt)[t] = 0;
    __syncthreads();
    const int s = blockIdx.x * 1024 + t;
    const int e = g_se[s];
    const unsigned mask = __match_any_sync(0xffffffffu, e);
    const int myrank = __popc(mask & ((1u << l) - 1));
    if (l == __ffs(mask) - 1) shcnt[w][e] = __popc(mask);
    __syncthreads();
    int r = g_boff[blockIdx.x * NE + e] + myrank;
    for (int w2 = 0; w2 < w; w2++) r += shcnt[w2][e];
    g_sp[s] = (r < CAP) ? r : -1;
}

// ---------------------------------------------------------------------------
// Scatter: x rows -> fp16 into exp slot. ILP=2 (two slots per block).
// ---------------------------------------------------------------------------
__global__ void scatter_fp16(const float* __restrict__ x) {
    const int s0 = blockIdx.x * 2;
    const int t = threadIdx.x;

    const int p0 = g_sp[s0], p1 = g_sp[s0 + 1];
    const int e0 = g_se[s0], e1 = g_se[s0 + 1];
    const int tok0 = s0 >> 1, tok1 = (s0 + 1) >> 1;

    float4 v0, v1;
    if (p0 >= 0) v0 = ((const float4*)(x + (size_t)tok0 * DM))[t];
    if (p1 >= 0) v1 = ((const float4*)(x + (size_t)tok1 * DM))[t];

    if (p0 >= 0) {
        __half h[4] = { __float2half(v0.x), __float2half(v0.y),
                        __float2half(v0.z), __float2half(v0.w) };
        *(uint2*)&g_ax[((size_t)e0 * CAP + p0) * DM + t * 4] = *(uint2*)h;
    }
    if (p1 >= 0) {
        __half h[4] = { __float2half(v1.x), __float2half(v1.y),
                        __float2half(v1.z), __float2half(v1.w) };
        *(uint2*)&g_ax[((size_t)e1 * CAP + p1) * DM + t * 4] = *(uint2*)h;
    }
}

// ---------------------------------------------------------------------------
// Weight transpose -> fp16. which==0 (W1): interleave dest rows so that
//   dest row 2j   = fc column j         (a / silu input)
//   dest row 2j+1 = fc column j + 1536  (g / gate input)
// which==1 (W2): plain transpose.
// ---------------------------------------------------------------------------
__global__ void wsplit_kernel(const float* __restrict__ W, const int which,
                              const int K, const int N) {
    __shared__ float s[32][33];
    __half* D = which ? g_w2 : g_w1;
    const int e = blockIdx.z;
    const int n0 = blockIdx.x * 32, k0 = blockIdx.y * 32;
    const float* src = W + (size_t)e * K * N;
    const int tx = threadIdx.x, ty = threadIdx.y;   // 32 x 8

    int scol;
    if (which == 0) scol = (tx < 16) ? (n0 / 2 + tx) : (n0 / 2 + DH + (tx - 16));
    else            scol = n0 + tx;

    #pragma unroll
    for (int i = 0; i < 4; i++)
        s[ty + i*8][tx] = src[(size_t)(k0 + ty + i*8) * N + scol];
    __syncthreads();

    const size_t dbase = (size_t)e * N * K;
    #pragma unroll
    for (int i = 0; i < 4; i++) {
        const int r = ty + i*8;
        const int c = which == 0 ? ((r & 1) ? 16 + (r >> 1) : (r >> 1)) : r;
        D[dbase + (size_t)(n0 + r) * K + k0 + tx] = __float2half(s[tx][c]);
    }
}

// ---------------------------------------------------------------------------
// Persistent batched GEMM: C[e][M][N] = A[e][M][K] @ B[e][N][K]^T (fp16, f32 acc)
// which==0: epilogue = fused SwiGLU, smem-staged, fp16 -> g_hg.
// which==1: fp16 (half2) stores -> g_eo.
// ---------------------------------------------------------------------------
__device__ __forceinline__ void load_stage(
    uint32_t sdst,
    const __half* __restrict__ A, const __half* __restrict__ B,
    const int K, const int k0, const int tid)
{
    #pragma unroll
    for (int i = 0; i < 12; i++) {
        const int L = i * 256 + tid;          // 0..3071
        const int rid = L >> 3, q = L & 7;
        const __half* src;
        uint32_t dst;
        if (rid < 128) { src = A + (size_t)rid * K;                 dst = sdst +         rid * ROWB; }
        else           { const int r = rid - 128; src = B + (size_t)r * K; dst = sdst + 20480 + r * ROWB; }
        cp16(dst + q * 16, src + k0 + q * 8);
    }
}

__global__ void __launch_bounds__(256, 1)
gemm_mma(const int which, const int N, const int K)
{
    extern __shared__ char smem[];
    const uint32_t sb = smem_u32(smem);
    const int tid = threadIdx.x, wid = tid >> 5, lane = tid & 31;
    const int wm = wid & 1, wn = wid >> 1;          // 2 x 4 warp grid, warp 64x64
    const int gq = lane >> 2, tg = lane & 3;

    const __half *gA, *gB;
    if (which == 0) { gA = g_ax; gB = g_w1; }
    else            { gA = g_hg; gB = g_w2; }

    const int nbx = N / TN;
    const int per_e = nbx * (CAP / TM);
    const int NT = per_e * NE;
    const int NC = gridDim.x;
    const int myNT = (NT - (int)blockIdx.x + NC - 1) / NC;
    if (myNT <= 0) return;
    const int T = K / TK;                 // 16 (gemm1) / 24 (gemm2)
    const int G = myNT * T;

    // ---- loader state ----
    int l_t, l_tc = 0, l_tile = blockIdx.x;
    const __half *lA, *lB;
    {
        const int e = l_tile / per_e, r = l_tile % per_e;
        lA = gA + ((size_t)e * CAP + (r / nbx) * TM) * K;
        lB = gB + ((size_t)e * N + (r % nbx) * TN) * K;
    }
    load_stage(sb,           lA, lB, K, 0,  tid);  CP_COMMIT();
    load_stage(sb + STAGE_B, lA, lB, K, TK, tid);  CP_COMMIT();
    l_t = 2;

    const int lmr = lane & 15;
    const int lmk = (lane >> 4) << 3;

    int g = 0;
    int c_tile = blockIdx.x;
    for (int tc = 0; tc < myNT; tc++, c_tile += NC) {
        float acc[128];
        #pragma unroll
        for (int i = 0; i < 128; i++) acc[i] = 0.f;

        for (int t = 0; t < T; t++, g++) {
            if (g + 1 < G) asm volatile("cp.async.wait_group 1;" ::: "memory");
            else           asm volatile("cp.async.wait_group 0;" ::: "memory");
            __syncthreads();

            if (g + 2 < G) {
                load_stage(sb + ((g + 2) % 3) * STAGE_B, lA, lB, K, l_t * TK, tid);
                CP_COMMIT();
                if (++l_t == T) {
                    l_t = 0; l_tc++; l_tile += NC;
                    if (l_tc < myNT) {
                        const int e = l_tile / per_e, r = l_tile % per_e;
                        lA = gA + ((size_t)e * CAP + (r / nbx) * TM) * K;
                        lB = gB + ((size_t)e * N + (r % nbx) * TN) * K;
                    }
                }
            }

            const uint32_t sst = sb + (g % 3) * STAGE_B;
            #pragma unroll
            for (int kk = 0; kk < 4; kk++) {
                const uint32_t koff = (kk * 16 + lmk) * 2;
                const uint32_t aA = sst + (wm * 64 + lmr) * ROWB + koff;
                const uint32_t aB = sst + 20480 + (wn * 64 + lmr) * ROWB + koff;

                uint32_t ah[16], bh[16], q[4];
                LDSM4(&ah[0],  aA);
                LDSM4(&ah[4],  aA + 16 * ROWB);
                LDSM4(&ah[8],  aA + 32 * ROWB);
                LDSM4(&ah[12], aA + 48 * ROWB);
                #pragma unroll
                for (int u = 0; u < 4; u++) {
                    LDSM4(q, aB + u * 16 * ROWB);
                    bh[4*u+0] = q[0]; bh[4*u+1] = q[2]; bh[4*u+2] = q[1]; bh[4*u+3] = q[3];
                }
                #pragma unroll
                for (int i = 0; i < 4; i++)
                    #pragma unroll
                    for (int j = 0; j < 8; j++)
                        MMA16816(&acc[(i*8+j)*4], &ah[i*4], bh[2*j], bh[2*j+1]);
            }
        }

        // ---- epilogue for c_tile ----
        const int e = c_tile / per_e, r = c_tile % per_e;
        const int bm = (r / nbx) * TM, bn = (r % nbx) * TN;

        if (which == 0) {
            __half* EP = (__half*)(smem + EP_OFF);
            #pragma unroll
            for (int i = 0; i < 4; i++) {
                const int lr = wm * 64 + i * 16 + gq;
                #pragma unroll
                for (int j = 0; j < 8; j++) {
                    const int lc = wn * 32 + j * 4 + tg;
                    const float* c = &acc[(i*8+j)*4];
                    const float h0 = (c[0] / (1.f + expf(-c[0]))) * c[1];
                    const float h1 = (c[2] / (1.f + expf(-c[2]))) * c[3];
                    EP[lr * 136 + lc]       = __float2half(h0);
                    EP[(lr + 8) * 136 + lc] = __float2half(h1);
                }
            }
            __syncthreads();
            __half* HG = g_hg + (size_t)e * CAP * DH + (bn >> 1);
            #pragma unroll
            for (int it = 0; it < 8; it++) {
                const int idx = it * 256 + tid;
                const int rr = idx >> 4, qq = idx & 15;
                *(uint4*)&HG[(size_t)(bm + rr) * DH + qq * 8] =
                    *(uint4*)&EP[rr * 136 + qq * 8];
            }
            __syncthreads();   // EP reuse safe next tile
        } else {
            __half* C = g_eo + (size_t)e * CAP * N;
            #pragma unroll
            for (int i = 0; i < 4; i++) {
                const int row = bm + wm * 64 + i * 16 + gq;
                #pragma unroll
                for (int j = 0; j < 8; j++) {
                    const int col = bn + wn * 64 + j * 8 + tg * 2;
                    const float* c = &acc[(i*8+j)*4];
                    *(__half2*)&C[(size_t)row * N + col] = __floats2half2_rn(c[0], c[1]);
                    *(__half2*)&C[(size_t)(row + 8) * N + col] = __floats2half2_rn(c[2], c[3]);
                }
            }
        }
    }
}

// ---------------------------------------------------------------------------
// Combine: out[n] = w0*eo[e0,p0] + w1*eo[e1,p1]   (eo is fp16)
// ---------------------------------------------------------------------------
__global__ void combine_kernel(float* __restrict__ out) {
    const int n = blockIdx.x;
    const int s0 = 2 * n;
    float w0 = g_sw[s0], w1 = g_sw[s0 + 1];
    int   p0 = g_sp[s0], p1 = g_sp[s0 + 1];
    const int e0 = g_se[s0], e1 = g_se[s0 + 1];
    if (p0 < 0) { w0 = 0.f; p0 = 0; }
    if (p1 < 0) { w1 = 0.f; p1 = 0; }
    const uint2 ua = *(const uint2*)&g_eo[((size_t)e0 * CAP + p0) * DM + threadIdx.x * 4];
    const uint2 ub = *(const uint2*)&g_eo[((size_t)e1 * CAP + p1) * DM + threadIdx.x * 4];
    const float2 a0 = __half22float2(*(const __half2*)&ua.x);
    const float2 a1 = __half22float2(*(const __half2*)&ua.y);
    const float2 b0 = __half22float2(*(const __half2*)&ub.x);
    const float2 b1 = __half22float2(*(const __half2*)&ub.y);
    float4 o;
    o.x = w0 * a0.x + w1 * b0.x;
    o.y = w0 * a0.y + w1 * b0.y;
    o.z = w0 * a1.x + w1 * b1.x;
    o.w = w0 * a1.y + w1 * b1.y;
    ((float4*)(out + (size_t)n * DM))[threadIdx.x] = o;
}

// ---------------------------------------------------------------------------
extern "C" void kernel_launch(void* const* d_in, const int* in_sizes, int n_in,
                              void* d_out, int out_size) {
    const float *x = nullptr, *wg = nullptr, *cfc = nullptr, *cpr = nullptr;
    for (int i = 0; i < n_in; i++) {
        switch (in_sizes[i]) {
            case 16777216: x   = (const float*)d_in[i]; break;  // [8,2048,1024]
            case 8192:     wg  = (const float*)d_in[i]; break;  // [1024,8]
            case 25165824: cfc = (const float*)d_in[i]; break;  // [8,1024,3072]
            case 12582912: cpr = (const float*)d_in[i]; break;  // [8,1536,1024]
        }
    }
    float* out = (float*)d_out;

    int nsm = 148;
    cudaDeviceGetAttribute(&nsm, cudaDevAttrMultiProcessorCount, 0);
    cudaFuncSetAttribute(gemm_mma, cudaFuncAttributeMaxDynamicSharedMemorySize, GEMM_SMEM);

    void* bcnt_ptr = nullptr;
    cudaGetSymbolAddress(&bcnt_ptr, g_bcnt);
    cudaMemsetAsync(bcnt_ptr, 0, NBLK * NE * sizeof(int));

    gate_kernel  <<<N_TOK / 4, 128>>>(x, wg);
    scan_kernel  <<<1, NE>>>();
    pos_kernel   <<<NBLK, 1024>>>();
    scatter_fp16 <<<NSLOT / 2, 256>>>(x);

    wsplit_kernel<<<dim3(DFF / 32, DM / 32, NE), dim3(32, 8)>>>(cfc, 0, DM, DFF);  // W1 (interleaved)
    wsplit_kernel<<<dim3(DM / 32, DH / 32, NE), dim3(32, 8)>>>(cpr, 1, DH, DM);    // W2

    gemm_mma<<<nsm, 256, GEMM_SMEM>>>(0, DFF, DM);   // fused H+SwiGLU -> g_hg
    gemm_mma<<<nsm, 256, GEMM_SMEM>>>(1, DM, DH);    // O = HG @ W2^T -> g_eo (fp16)

    combine_kernel<<<N_TOK, 256>>>(out);
}

// round 13
// speedup vs baseline: 1.0429x; 1.0375x over previous
#include <cuda_runtime.h>
#include <cuda_fp16.h>
#include <stdint.h>
#include <math.h>

// ---------------------------------------------------------------------------
// MoE: gate -> top2 route -> capacity dispatch -> 8x SwiGLU expert MLP -> combine
// Expert GEMMs: mma.sync fp16 (fp32 acc), persistent CTAs, TK=64, 3-slot ring.
// R13: R10 baseline (best measured) + two isolated validated wins only:
//      scatter ILP=2, ballot-based pos ranking. Everything else = R10.
// ---------------------------------------------------------------------------

#define N_TOK   16384
#define DM      1024
#define NE      8
#define CAP     4096
#define DFF     3072
#define DH      1536
#define NSLOT   (N_TOK * 2)
#define NBLK    32

// GEMM tiling
#define TM      128
#define TN      256
#define TK      64
#define ROWB    160                   // 128B data + 32B pad (conflict-free ldmatrix)
#define STAGE_B 61440                 // A: 128*160  +  B: 256*160
#define EP_OFF  (3 * STAGE_B)         // epilogue staging buffer (gemm1)
#define GEMM_SMEM (EP_OFF + 128 * 136 * 2)   // 219136

// ---- scratch (device globals: allocation-free rule) ----
__device__ float  g_eo[(size_t)NE * CAP * DM];     // expert output (fp32)
__device__ __half g_ax[(size_t)NE * CAP * DM];     // dispatched x (fp16)
__device__ __half g_hg[(size_t)NE * CAP * DH];     // swiglu out (fp16)
__device__ __half g_w1[(size_t)NE * DFF * DM];     // W1^T interleaved [E][3072][1024]
__device__ __half g_w2[(size_t)NE * DM * DH];      // W2^T [E][1024][1536]
__device__ int   g_se[NSLOT];
__device__ float g_sw[NSLOT];
__device__ int   g_sp[NSLOT];
__device__ int   g_bcnt[NBLK * NE];
__device__ int   g_boff[NBLK * NE];

// ---------------------------------------------------------------------------
// helpers
// ---------------------------------------------------------------------------
__device__ __forceinline__ uint32_t smem_u32(const void* p) {
    uint32_t a;
    asm("{ .reg .u64 t; cvta.to.shared.u64 t, %1; cvt.u32.u64 %0, t; }"
        : "=r"(a) : "l"(p));
    return a;
}
__device__ __forceinline__ void cp16(uint32_t dst, const void* src) {
    asm volatile("cp.async.cg.shared.global [%0], [%1], 16;" :: "r"(dst), "l"(src));
}
#define CP_COMMIT() asm volatile("cp.async.commit_group;" ::: "memory")

#define LDSM4(v, addr) \
    asm volatile("ldmatrix.sync.aligned.m8n8.x4.shared.b16 {%0,%1,%2,%3}, [%4];" \
        : "=r"((v)[0]), "=r"((v)[1]), "=r"((v)[2]), "=r"((v)[3]) : "r"(addr))

#define MMA16816(c, a, b0, b1) \
    asm volatile("mma.sync.aligned.m16n8k16.row.col.f32.f16.f16.f32 " \
        "{%0,%1,%2,%3}, {%4,%5,%6,%7}, {%8,%9}, {%0,%1,%2,%3};" \
        : "+f"((c)[0]), "+f"((c)[1]), "+f"((c)[2]), "+f"((c)[3]) \
        : "r"((a)[0]), "r"((a)[1]), "r"((a)[2]), "r"((a)[3]), "r"(b0), "r"(b1))

// ---------------------------------------------------------------------------
// Gate: logits -> softmax -> top2 (ties: lowest index)
// ---------------------------------------------------------------------------
__global__ void gate_kernel(const float* __restrict__ x, const float* __restrict__ wg) {
    __shared__ float wgs[NE][DM];
    const int tid = threadIdx.x;
    for (int i = tid; i < NE * DM; i += blockDim.x)
        wgs[i & 7][i >> 3] = wg[i];
    __syncthreads();

    const int warp = tid >> 5, lane = tid & 31;
    const int n = blockIdx.x * 4 + warp;

    float acc[NE];
    #pragma unroll
    for (int e = 0; e < NE; e++) acc[e] = 0.f;
    const float* xr = x + (size_t)n * DM;
    for (int j = lane; j < DM; j += 32) {
        const float xv = xr[j];
        #pragma unroll
        for (int e = 0; e < NE; e++) acc[e] += xv * wgs[e][j];
    }
    #pragma unroll
    for (int off = 16; off; off >>= 1)
        #pragma unroll
        for (int e = 0; e < NE; e++)
            acc[e] += __shfl_xor_sync(0xffffffffu, acc[e], off);

    if (lane == 0) {
        float m = acc[0];
        #pragma unroll
        for (int e = 1; e < NE; e++) m = fmaxf(m, acc[e]);
        float p[NE], s = 0.f;
        #pragma unroll
        for (int e = 0; e < NE; e++) { p[e] = expf(acc[e] - m); s += p[e]; }
        const float inv = 1.f / s;
        #pragma unroll
        for (int e = 0; e < NE; e++) p[e] *= inv;
        int e1 = 0;
        #pragma unroll
        for (int e = 1; e < NE; e++) if (p[e] > p[e1]) e1 = e;
        int e2 = (e1 == 0) ? 1 : 0;
        #pragma unroll
        for (int e = 0; e < NE; e++) if (e != e1 && p[e] > p[e2]) e2 = e;
        g_se[2*n]   = e1;  g_sw[2*n]   = p[e1];
        g_se[2*n+1] = e2;  g_sw[2*n+1] = p[e2];
    }
}

// ---------------------------------------------------------------------------
// Count: per-block expert histogram (as in R10 — no gate fusion)
// ---------------------------------------------------------------------------
__global__ void count_kernel() {
    __shared__ int c[NE];
    if (threadIdx.x < NE) c[threadIdx.x] = 0;
    __syncthreads();
    atomicAdd(&c[g_se[blockIdx.x * 1024 + threadIdx.x]], 1);
    __syncthreads();
    if (threadIdx.x < NE) g_bcnt[blockIdx.x * NE + threadIdx.x] = c[threadIdx.x];
}

// ---------------------------------------------------------------------------
// Scan: per-expert exclusive block offsets (8 threads)
// ---------------------------------------------------------------------------
__global__ void scan_kernel() {
    const int e = threadIdx.x;
    int run = 0;
    for (int b = 0; b < NBLK; b++) { g_boff[b * NE + e] = run; run += g_bcnt[b * NE + e]; }
}

// ---------------------------------------------------------------------------
// Pos: ballot-based intra-block rank (match_any + warp histograms)
// ---------------------------------------------------------------------------
__global__ void pos_kernel() {
    __shared__ int shcnt[32][NE];
    const int t = threadIdx.x, w = t >> 5, l = t & 31;
    if (t < 32 * NE) ((int*)shcnt)[t] = 0;
    __syncthreads();
    const int s = blockIdx.x * 1024 + t;
    const int e = g_se[s];
    const unsigned mask = __match_any_sync(0xffffffffu, e);
    const int myrank = __popc(mask & ((1u << l) - 1));
    if (l == __ffs(mask) - 1) shcnt[w][e] = __popc(mask);
    __syncthreads();
    int r = g_boff[blockIdx.x * NE + e] + myrank;
    for (int w2 = 0; w2 < w; w2++) r += shcnt[w2][e];
    g_sp[s] = (r < CAP) ? r : -1;
}

// ---------------------------------------------------------------------------
// Scatter: x rows -> fp16 into exp slot. ILP=2 (two slots per block).
// ---------------------------------------------------------------------------
__global__ void scatter_fp16(const float* __restrict__ x) {
    const int s0 = blockIdx.x * 2;
    const int t = threadIdx.x;

    const int p0 = g_sp[s0], p1 = g_sp[s0 + 1];
    const int e0 = g_se[s0], e1 = g_se[s0 + 1];
    const int tok0 = s0 >> 1, tok1 = (s0 + 1) >> 1;

    float4 v0, v1;
    if (p0 >= 0) v0 = ((const float4*)(x + (size_t)tok0 * DM))[t];
    if (p1 >= 0) v1 = ((const float4*)(x + (size_t)tok1 * DM))[t];

    if (p0 >= 0) {
        __half h[4] = { __float2half(v0.x), __float2half(v0.y),
                        __float2half(v0.z), __float2half(v0.w) };
        *(uint2*)&g_ax[((size_t)e0 * CAP + p0) * DM + t * 4] = *(uint2*)h;
    }
    if (p1 >= 0) {
        __half h[4] = { __float2half(v1.x), __float2half(v1.y),
                        __float2half(v1.z), __float2half(v1.w) };
        *(uint2*)&g_ax[((size_t)e1 * CAP + p1) * DM + t * 4] = *(uint2*)h;
    }
}

// ---------------------------------------------------------------------------
// Weight transpose -> fp16. which==0 (W1): interleave dest rows so that
//   dest row 2j   = fc column j         (a / silu input)
//   dest row 2j+1 = fc column j + 1536  (g / gate input)
// which==1 (W2): plain transpose.
// ---------------------------------------------------------------------------
__global__ void wsplit_kernel(const float* __restrict__ W, const int which,
                              const int K, const int N) {
    __shared__ float s[32][33];
    __half* D = which ? g_w2 : g_w1;
    const int e = blockIdx.z;
    const int n0 = blockIdx.x * 32, k0 = blockIdx.y * 32;
    const float* src = W + (size_t)e * K * N;
    const int tx = threadIdx.x, ty = threadIdx.y;   // 32 x 8

    int scol;
    if (which == 0) scol = (tx < 16) ? (n0 / 2 + tx) : (n0 / 2 + DH + (tx - 16));
    else            scol = n0 + tx;

    #pragma unroll
    for (int i = 0; i < 4; i++)
        s[ty + i*8][tx] = src[(size_t)(k0 + ty + i*8) * N + scol];
    __syncthreads();

    const size_t dbase = (size_t)e * N * K;
    #pragma unroll
    for (int i = 0; i < 4; i++) {
        const int r = ty + i*8;
        const int c = which == 0 ? ((r & 1) ? 16 + (r >> 1) : (r >> 1)) : r;
        D[dbase + (size_t)(n0 + r) * K + k0 + tx] = __float2half(s[tx][c]);
    }
}

// ---------------------------------------------------------------------------
// Persistent batched GEMM: C[e][M][N] = A[e][M][K] @ B[e][N][K]^T (fp16, f32 acc)
// Grid = numSM CTAs, continuous 3-slot cp.async ring, TK=64 K-tiles.
// which==0: epilogue = fused SwiGLU, smem-staged, fp16 -> g_hg.
// which==1: direct fp32 stores -> g_eo.
// ---------------------------------------------------------------------------
__device__ __forceinline__ void load_stage(
    uint32_t sdst,
    const __half* __restrict__ A, const __half* __restrict__ B,
    const int K, const int k0, const int tid)
{
    #pragma unroll
    for (int i = 0; i < 12; i++) {
        const int L = i * 256 + tid;          // 0..3071
        const int rid = L >> 3, q = L & 7;
        const __half* src;
        uint32_t dst;
        if (rid < 128) { src = A + (size_t)rid * K;                 dst = sdst +         rid * ROWB; }
        else           { const int r = rid - 128; src = B + (size_t)r * K; dst = sdst + 20480 + r * ROWB; }
        cp16(dst + q * 16, src + k0 + q * 8);
    }
}

__global__ void __launch_bounds__(256, 1)
gemm_mma(const int which, const int N, const int K)
{
    extern __shared__ char smem[];
    const uint32_t sb = smem_u32(smem);
    const int tid = threadIdx.x, wid = tid >> 5, lane = tid & 31;
    const int wm = wid & 1, wn = wid >> 1;          // 2 x 4 warp grid, warp 64x64
    const int gq = lane >> 2, tg = lane & 3;

    const __half *gA, *gB;
    if (which == 0) { gA = g_ax; gB = g_w1; }
    else            { gA = g_hg; gB = g_w2; }

    const int nbx = N / TN;
    const int per_e = nbx * (CAP / TM);
    const int NT = per_e * NE;
    const int NC = gridDim.x;
    const int myNT = (NT - (int)blockIdx.x + NC - 1) / NC;
    if (myNT <= 0) return;
    const int T = K / TK;                 // 16 (gemm1) / 24 (gemm2)
    const int G = myNT * T;

    // ---- loader state ----
    int l_t, l_tc = 0, l_tile = blockIdx.x;
    const __half *lA, *lB;
    {
        const int e = l_tile / per_e, r = l_tile % per_e;
        lA = gA + ((size_t)e * CAP + (r / nbx) * TM) * K;
        lB = gB + ((size_t)e * N + (r % nbx) * TN) * K;
    }
    load_stage(sb,           lA, lB, K, 0,  tid);  CP_COMMIT();
    load_stage(sb + STAGE_B, lA, lB, K, TK, tid);  CP_COMMIT();
    l_t = 2;

    const int lmr = lane & 15;
    const int lmk = (lane >> 4) << 3;

    int g = 0;
    int c_tile = blockIdx.x;
    for (int tc = 0; tc < myNT; tc++, c_tile += NC) {
        float acc[128];
        #pragma unroll
        for (int i = 0; i < 128; i++) acc[i] = 0.f;

        for (int t = 0; t < T; t++, g++) {
            if (g + 1 < G) asm volatile("cp.async.wait_group 1;" ::: "memory");
            else           asm volatile("cp.async.wait_group 0;" ::: "memory");
            __syncthreads();

            if (g + 2 < G) {
                load_stage(sb + ((g + 2) % 3) * STAGE_B, lA, lB, K, l_t * TK, tid);
                CP_COMMIT();
                if (++l_t == T) {
                    l_t = 0; l_tc++; l_tile += NC;
                    if (l_tc < myNT) {
                        const int e = l_tile / per_e, r = l_tile % per_e;
                        lA = gA + ((size_t)e * CAP + (r / nbx) * TM) * K;
                        lB = gB + ((size_t)e * N + (r % nbx) * TN) * K;
                    }
                }
            }

            const uint32_t sst = sb + (g % 3) * STAGE_B;
            #pragma unroll
            for (int kk = 0; kk < 4; kk++) {
                const uint32_t koff = (kk * 16 + lmk) * 2;
                const uint32_t aA = sst + (wm * 64 + lmr) * ROWB + koff;
                const uint32_t aB = sst + 20480 + (wn * 64 + lmr) * ROWB + koff;

                uint32_t ah[16], bh[16], q[4];
                LDSM4(&ah[0],  aA);
                LDSM4(&ah[4],  aA + 16 * ROWB);
                LDSM4(&ah[8],  aA + 32 * ROWB);
                LDSM4(&ah[12], aA + 48 * ROWB);
                #pragma unroll
                for (int u = 0; u < 4; u++) {
                    LDSM4(q, aB + u * 16 * ROWB);
                    bh[4*u+0] = q[0]; bh[4*u+1] = q[2]; bh[4*u+2] = q[1]; bh[4*u+3] = q[3];
                }
                #pragma unroll
                for (int i = 0; i < 4; i++)
                    #pragma unroll
                    for (int j = 0; j < 8; j++)
                        MMA16816(&acc[(i*8+j)*4], &ah[i*4], bh[2*j], bh[2*j+1]);
            }
        }

        // ---- epilogue for c_tile ----
        const int e = c_tile / per_e, r = c_tile % per_e;
        const int bm = (r / nbx) * TM, bn = (r % nbx) * TN;

        if (which == 0) {
            // Fused SwiGLU -> smem stage [128][136] halves -> coalesced stores
            __half* EP = (__half*)(smem + EP_OFF);
            #pragma unroll
            for (int i = 0; i < 4; i++) {
                const int lr = wm * 64 + i * 16 + gq;
                #pragma unroll
                for (int j = 0; j < 8; j++) {
                    const int lc = wn * 32 + j * 4 + tg;
                    const float* c = &acc[(i*8+j)*4];
                    const float h0 = (c[0] / (1.f + expf(-c[0]))) * c[1];
                    const float h1 = (c[2] / (1.f + expf(-c[2]))) * c[3];
                    EP[lr * 136 + lc]       = __float2half(h0);
                    EP[(lr + 8) * 136 + lc] = __float2half(h1);
                }
            }
            __syncthreads();
            __half* HG = g_hg + (size_t)e * CAP * DH + (bn >> 1);
            #pragma unroll
            for (int it = 0; it < 8; it++) {
                const int idx = it * 256 + tid;       // 128 rows x 16 uint4
                const int rr = idx >> 4, qq = idx & 15;
                *(uint4*)&HG[(size_t)(bm + rr) * DH + qq * 8] =
                    *(uint4*)&EP[rr * 136 + qq * 8];
            }
            __syncthreads();   // EP reuse safe next tile
        } else {
            float* C = g_eo + (size_t)e * CAP * N;
            #pragma unroll
            for (int i = 0; i < 4; i++) {
                const int row = bm + wm * 64 + i * 16 + gq;
                #pragma unroll
                for (int j = 0; j < 8; j++) {
                    const int col = bn + wn * 64 + j * 8 + tg * 2;
                    float* p = C + (size_t)row * N + col;
                    const float* c = &acc[(i*8+j)*4];
                    *(float2*)p           = make_float2(c[0], c[1]);
                    *(float2*)(p + 8 * N) = make_float2(c[2], c[3]);
                }
            }
        }
    }
}

// ---------------------------------------------------------------------------
// Combine: out[n] = w0*eo[e0,p0] + w1*eo[e1,p1]   (eo fp32, as in R10)
// ---------------------------------------------------------------------------
__global__ void combine_kernel(float* __restrict__ out) {
    const int n = blockIdx.x;
    const int s0 = 2 * n;
    float w0 = g_sw[s0], w1 = g_sw[s0 + 1];
    int   p0 = g_sp[s0], p1 = g_sp[s0 + 1];
    const int e0 = g_se[s0], e1 = g_se[s0 + 1];
    if (p0 < 0) { w0 = 0.f; p0 = 0; }
    if (p1 < 0) { w1 = 0.f; p1 = 0; }
    const float4 a = ((const float4*)(g_eo + ((size_t)e0 * CAP + p0) * DM))[threadIdx.x];
    const float4 b = ((const float4*)(g_eo + ((size_t)e1 * CAP + p1) * DM))[threadIdx.x];
    float4 o;
    o.x = w0 * a.x + w1 * b.x;
    o.y = w0 * a.y + w1 * b.y;
    o.z = w0 * a.z + w1 * b.z;
    o.w = w0 * a.w + w1 * b.w;
    ((float4*)(out + (size_t)n * DM))[threadIdx.x] = o;
}

// ---------------------------------------------------------------------------
extern "C" void kernel_launch(void* const* d_in, const int* in_sizes, int n_in,
                              void* d_out, int out_size) {
    const float *x = nullptr, *wg = nullptr, *cfc = nullptr, *cpr = nullptr;
    for (int i = 0; i < n_in; i++) {
        switch (in_sizes[i]) {
            case 16777216: x   = (const float*)d_in[i]; break;  // [8,2048,1024]
            case 8192:     wg  = (const float*)d_in[i]; break;  // [1024,8]
            case 25165824: cfc = (const float*)d_in[i]; break;  // [8,1024,3072]
            case 12582912: cpr = (const float*)d_in[i]; break;  // [8,1536,1024]
        }
    }
    float* out = (float*)d_out;

    int nsm = 148;
    cudaDeviceGetAttribute(&nsm, cudaDevAttrMultiProcessorCount, 0);
    cudaFuncSetAttribute(gemm_mma, cudaFuncAttributeMaxDynamicSharedMemorySize, GEMM_SMEM);

    gate_kernel  <<<N_TOK / 4, 128>>>(x, wg);
    count_kernel <<<NBLK, 1024>>>();
    scan_kernel  <<<1, NE>>>();
    pos_kernel   <<<NBLK, 1024>>>();
    scatter_fp16 <<<NSLOT / 2, 256>>>(x);

    wsplit_kernel<<<dim3(DFF / 32, DM / 32, NE), dim3(32, 8)>>>(cfc, 0, DM, DFF);  // W1 (interleaved)
    wsplit_kernel<<<dim3(DM / 32, DH / 32, NE), dim3(32, 8)>>>(cpr, 1, DH, DM);    // W2

    gemm_mma<<<nsm, 256, GEMM_SMEM>>>(0, DFF, DM);   // fused H+SwiGLU -> g_hg
    gemm_mma<<<nsm, 256, GEMM_SMEM>>>(1, DM, DH);    // O = HG @ W2^T -> g_eo (fp32)

    combine_kernel<<<N_TOK, 256>>>(out);
}